// round 1
// baseline (speedup 1.0000x reference)
#include <cuda_runtime.h>
#include <stdint.h>
#include <math.h>

// ---------------------------------------------------------------------------
// AttentionBlock: GroupNorm -> QKV (1x1 conv) -> softmax(QK^T/sqrt(C)) V -> proj + x
// B=4, H=W=64 (seq=4096), C=512, G=32
// TF32 mma.sync GEMMs, fp32 accumulate/epilogues.
// ---------------------------------------------------------------------------

#define SEQ   4096
#define CDIM  512
#define BATCH 4
#define NTOK  (BATCH * SEQ)          // 16384
#define GROUPS 32
#define EPSGN 1e-5f

// Scratch (allocation-free rule: __device__ globals)
__device__ float g_xn[NTOK * CDIM];
__device__ float g_q [NTOK * CDIM];
__device__ float g_k [NTOK * CDIM];
__device__ float g_v [NTOK * CDIM];
__device__ float g_at[NTOK * CDIM];
__device__ float g_sc[(long)BATCH * SEQ * SEQ];   // 268 MB
__device__ float g_mean[BATCH * GROUPS];
__device__ float g_rstd[BATCH * GROUPS];

// ---------------------------------------------------------------------------
// helpers
// ---------------------------------------------------------------------------
__device__ __forceinline__ uint32_t f2tf(float x) {
    uint32_t u;
    asm("cvt.rna.tf32.f32 %0, %1;" : "=r"(u) : "f"(x));
    return u;
}
__device__ __forceinline__ uint4 cvt4(float4 v) {
    uint4 r;
    r.x = f2tf(v.x); r.y = f2tf(v.y); r.z = f2tf(v.z); r.w = f2tf(v.w);
    return r;
}
__device__ __forceinline__ void mma8(float* c, const uint32_t* a, const uint32_t* b) {
    asm volatile(
        "mma.sync.aligned.m16n8k8.row.col.f32.tf32.tf32.f32 "
        "{%0,%1,%2,%3},{%4,%5,%6,%7},{%8,%9},{%0,%1,%2,%3};\n"
        : "+f"(c[0]), "+f"(c[1]), "+f"(c[2]), "+f"(c[3])
        : "r"(a[0]), "r"(a[1]), "r"(a[2]), "r"(a[3]), "r"(b[0]), "r"(b[1]));
}

// ---------------------------------------------------------------------------
// GEMM:  C[M,N] = scale * A[M,K] @ op(B)  (+bias[N]) (+res)
// BT=false: B is [K,N] row-major.  BT=true: B is [N,K] row-major (C = A B^T).
// Block tile 128x64x16, 8 warps (4x2) each 32x32, double-buffered smem.
// All dims here are multiples of tile sizes -> no bounds checks.
// ---------------------------------------------------------------------------
template<bool BT, bool BIAS, bool RES>
__global__ __launch_bounds__(256)
void gemm_tf32(const float* __restrict__ A, const float* __restrict__ Bm,
               const float* __restrict__ bias, const float* __restrict__ res,
               float* __restrict__ C, int N, int K, float scale,
               long sA, long sB, long sC)
{
    constexpr int BM = 128, BN = 64, BK = 16;
    constexpr int AST = 28;                 // A smem stride (conflict-free + 16B aligned)
    constexpr int BST = BT ? 28 : 72;       // B smem stride
    constexpr int BROWS = BT ? 64 : 16;

    __shared__ __align__(16) uint32_t As[2][BM * AST];
    __shared__ __align__(16) uint32_t Bs[2][BROWS * BST];

    const int t = threadIdx.x;
    A += (long)blockIdx.z * sA;
    Bm += (long)blockIdx.z * sB;
    C += (long)blockIdx.z * sC;

    const int bm = blockIdx.y * BM;
    const int bn = blockIdx.x * BN;

    // gmem load indices
    const int ar = t >> 2;            // 0..63  (rows ar, ar+64)
    const int ak = (t & 3) << 2;      // 0,4,8,12
    const int br  = BT ? (t >> 2) : (t >> 4);
    const int bk_ = BT ? ((t & 3) << 2) : ((t & 15) << 2);

    const int warp = t >> 5, lane = t & 31;
    const int wm = (warp >> 1) * 32;
    const int wn = (warp & 1) * 32;
    const int gid = lane >> 2;        // 0..7
    const int tq  = lane & 3;         // 0..3

    float acc[2][4][4];
#pragma unroll
    for (int mi = 0; mi < 2; mi++)
#pragma unroll
        for (int ni = 0; ni < 4; ni++)
#pragma unroll
            for (int j = 0; j < 4; j++) acc[mi][ni][j] = 0.f;

    const int KB = K / BK;
    float4 la0, la1, lb0;

    auto ldg = [&](int kb) {
        const int k0 = kb * BK;
        la0 = *(const float4*)(A + (long)(bm + ar) * K + k0 + ak);
        la1 = *(const float4*)(A + (long)(bm + ar + 64) * K + k0 + ak);
        if (BT) lb0 = *(const float4*)(Bm + (long)(bn + br) * K + k0 + bk_);
        else    lb0 = *(const float4*)(Bm + (long)(k0 + br) * N + bn + bk_);
    };
    auto sts = [&](int buf) {
        *(uint4*)&As[buf][ar * AST + ak]        = cvt4(la0);
        *(uint4*)&As[buf][(ar + 64) * AST + ak] = cvt4(la1);
        *(uint4*)&Bs[buf][br * BST + bk_]       = cvt4(lb0);
    };

    ldg(0);
    sts(0);
    __syncthreads();

    for (int kb = 0; kb < KB; kb++) {
        const int cur = kb & 1;
        if (kb + 1 < KB) ldg(kb + 1);

#pragma unroll
        for (int ks = 0; ks < BK; ks += 8) {
            uint32_t af[2][4], bf[4][2];
#pragma unroll
            for (int mi = 0; mi < 2; mi++) {
                const int r = wm + mi * 16 + gid;
                af[mi][0] = As[cur][r * AST + ks + tq];
                af[mi][1] = As[cur][(r + 8) * AST + ks + tq];
                af[mi][2] = As[cur][r * AST + ks + tq + 4];
                af[mi][3] = As[cur][(r + 8) * AST + ks + tq + 4];
            }
#pragma unroll
            for (int ni = 0; ni < 4; ni++) {
                const int c = wn + ni * 8 + gid;
                if (BT) {
                    bf[ni][0] = Bs[cur][c * BST + ks + tq];
                    bf[ni][1] = Bs[cur][c * BST + ks + tq + 4];
                } else {
                    bf[ni][0] = Bs[cur][(ks + tq) * BST + c];
                    bf[ni][1] = Bs[cur][(ks + tq + 4) * BST + c];
                }
            }
#pragma unroll
            for (int mi = 0; mi < 2; mi++)
#pragma unroll
                for (int ni = 0; ni < 4; ni++)
                    mma8(acc[mi][ni], af[mi], bf[ni]);
        }

        if (kb + 1 < KB) {
            sts(cur ^ 1);
            __syncthreads();
        }
    }

    // epilogue
#pragma unroll
    for (int mi = 0; mi < 2; mi++)
#pragma unroll
        for (int ni = 0; ni < 4; ni++) {
            const int r0 = bm + wm + mi * 16 + gid;
            const int c0 = bn + wn + ni * 8 + tq * 2;
            float2 v0 = make_float2(acc[mi][ni][0] * scale, acc[mi][ni][1] * scale);
            float2 v1 = make_float2(acc[mi][ni][2] * scale, acc[mi][ni][3] * scale);
            if (BIAS) {
                const float b0 = bias[c0], b1 = bias[c0 + 1];
                v0.x += b0; v0.y += b1; v1.x += b0; v1.y += b1;
            }
            if (RES) {
                v0.x += res[(long)r0 * N + c0];
                v0.y += res[(long)r0 * N + c0 + 1];
                v1.x += res[(long)(r0 + 8) * N + c0];
                v1.y += res[(long)(r0 + 8) * N + c0 + 1];
            }
            *(float2*)&C[(long)r0 * N + c0] = v0;
            *(float2*)&C[(long)(r0 + 8) * N + c0] = v1;
        }
}

// ---------------------------------------------------------------------------
// GroupNorm statistics: one block per (batch, group); 4096 px * 16 ch = 65536 el
// ---------------------------------------------------------------------------
__global__ __launch_bounds__(256)
void gn_stats(const float* __restrict__ x, float* __restrict__ mv, float* __restrict__ rv)
{
    __shared__ float rs[8], rs2[8];
    const int bg = blockIdx.x;
    const float* base = x + (long)(bg >> 5) * (SEQ * (long)CDIM) + (bg & 31) * 16;
    float s = 0.f, s2 = 0.f;
    for (int j = threadIdx.x; j < 16384; j += 256) {   // float4 index
        const float4 v = *(const float4*)(base + (long)(j >> 2) * CDIM + ((j & 3) << 2));
        s  += v.x + v.y + v.z + v.w;
        s2 += v.x * v.x + v.y * v.y + v.z * v.z + v.w * v.w;
    }
#pragma unroll
    for (int o = 16; o; o >>= 1) {
        s  += __shfl_xor_sync(0xffffffffu, s, o);
        s2 += __shfl_xor_sync(0xffffffffu, s2, o);
    }
    const int lane = threadIdx.x & 31, w = threadIdx.x >> 5;
    if (lane == 0) { rs[w] = s; rs2[w] = s2; }
    __syncthreads();
    if (threadIdx.x == 0) {
        float ts = 0.f, ts2 = 0.f;
#pragma unroll
        for (int i = 0; i < 8; i++) { ts += rs[i]; ts2 += rs2[i]; }
        const float inv_n = 1.f / 65536.f;
        const float mean = ts * inv_n;
        const float var = ts2 * inv_n - mean * mean;
        mv[bg] = mean;
        rv[bg] = rsqrtf(var + EPSGN);
    }
}

__global__ __launch_bounds__(256)
void gn_apply(const float* __restrict__ x, const float* __restrict__ gamma,
              const float* __restrict__ beta, const float* __restrict__ mv,
              const float* __restrict__ rv, float* __restrict__ xn)
{
    const long i4 = (long)blockIdx.x * 256 + threadIdx.x;   // float4 index
    const int c4 = (int)(i4 & 127);                         // 128 float4 per pixel
    const long pix = i4 >> 7;
    const int b = (int)(pix >> 12);
    const int bg = b * 32 + (c4 >> 2);                      // group = (4*c4)/16
    const float m = mv[bg], r = rv[bg];
    const float4 v  = ((const float4*)x)[i4];
    const float4 ga = ((const float4*)gamma)[c4];
    const float4 be = ((const float4*)beta)[c4];
    float4 o;
    o.x = (v.x - m) * r * ga.x + be.x;
    o.y = (v.y - m) * r * ga.y + be.y;
    o.z = (v.z - m) * r * ga.z + be.z;
    o.w = (v.w - m) * r * ga.w + be.w;
    ((float4*)xn)[i4] = o;
}

// ---------------------------------------------------------------------------
// Row softmax over 4096 elems, one block per row; values stay in registers.
// ---------------------------------------------------------------------------
__global__ __launch_bounds__(256)
void softmax_rows(float* __restrict__ s)
{
    __shared__ float red[8];
    float* p = s + (long)blockIdx.x * SEQ;
    const int t = threadIdx.x;
    float4 v[4];
#pragma unroll
    for (int j = 0; j < 4; j++) v[j] = ((float4*)p)[t + 256 * j];

    float m = -1e30f;
#pragma unroll
    for (int j = 0; j < 4; j++) {
        m = fmaxf(m, fmaxf(fmaxf(v[j].x, v[j].y), fmaxf(v[j].z, v[j].w)));
    }
#pragma unroll
    for (int o = 16; o; o >>= 1) m = fmaxf(m, __shfl_xor_sync(0xffffffffu, m, o));
    if ((t & 31) == 0) red[t >> 5] = m;
    __syncthreads();
    m = red[0];
#pragma unroll
    for (int i = 1; i < 8; i++) m = fmaxf(m, red[i]);
    __syncthreads();

    float sum = 0.f;
#pragma unroll
    for (int j = 0; j < 4; j++) {
        v[j].x = expf(v[j].x - m); sum += v[j].x;
        v[j].y = expf(v[j].y - m); sum += v[j].y;
        v[j].z = expf(v[j].z - m); sum += v[j].z;
        v[j].w = expf(v[j].w - m); sum += v[j].w;
    }
#pragma unroll
    for (int o = 16; o; o >>= 1) sum += __shfl_xor_sync(0xffffffffu, sum, o);
    if ((t & 31) == 0) red[t >> 5] = sum;
    __syncthreads();
    float tot = 0.f;
#pragma unroll
    for (int i = 0; i < 8; i++) tot += red[i];
    const float inv = 1.f / tot;
#pragma unroll
    for (int j = 0; j < 4; j++) {
        v[j].x *= inv; v[j].y *= inv; v[j].z *= inv; v[j].w *= inv;
        ((float4*)p)[t + 256 * j] = v[j];
    }
}

// ---------------------------------------------------------------------------
// launcher
// ---------------------------------------------------------------------------
extern "C" void kernel_launch(void* const* d_in, const int* in_sizes, int n_in,
                              void* d_out, int out_size)
{
    const float* x     = (const float*)d_in[0];
    const float* gamma = (const float*)d_in[1];
    const float* beta  = (const float*)d_in[2];
    const float* Wq    = (const float*)d_in[3];
    const float* bq    = (const float*)d_in[4];
    const float* Wk    = (const float*)d_in[5];
    const float* bk    = (const float*)d_in[6];
    const float* Wv    = (const float*)d_in[7];
    const float* bv    = (const float*)d_in[8];
    const float* Wp    = (const float*)d_in[9];
    const float* bp    = (const float*)d_in[10];
    float* out = (float*)d_out;

    void *pxn, *pq, *pk, *pv, *pat, *psc, *pm, *pr;
    cudaGetSymbolAddress(&pxn, g_xn);
    cudaGetSymbolAddress(&pq,  g_q);
    cudaGetSymbolAddress(&pk,  g_k);
    cudaGetSymbolAddress(&pv,  g_v);
    cudaGetSymbolAddress(&pat, g_at);
    cudaGetSymbolAddress(&psc, g_sc);
    cudaGetSymbolAddress(&pm,  g_mean);
    cudaGetSymbolAddress(&pr,  g_rstd);
    float* xn = (float*)pxn;
    float* q  = (float*)pq;
    float* k  = (float*)pk;
    float* v  = (float*)pv;
    float* at = (float*)pat;
    float* sc = (float*)psc;
    float* mv = (float*)pm;
    float* rv = (float*)pr;

    // 1) GroupNorm
    gn_stats<<<BATCH * GROUPS, 256>>>(x, mv, rv);
    gn_apply<<<(NTOK * CDIM) / (256 * 4), 256>>>(x, gamma, beta, mv, rv, xn);

    // 2) QKV projections: [16384,512] @ [512,512] + bias
    {
        dim3 g(CDIM / 64, NTOK / 128, 1);
        gemm_tf32<false, true, false><<<g, 256>>>(xn, Wq, bq, nullptr, q, CDIM, CDIM, 1.f, 0, 0, 0);
        gemm_tf32<false, true, false><<<g, 256>>>(xn, Wk, bk, nullptr, k, CDIM, CDIM, 1.f, 0, 0, 0);
        gemm_tf32<false, true, false><<<g, 256>>>(xn, Wv, bv, nullptr, v, CDIM, CDIM, 1.f, 0, 0, 0);
    }

    // 3) scores = Q K^T / sqrt(C), batched over 4
    {
        dim3 g(SEQ / 64, SEQ / 128, BATCH);
        gemm_tf32<true, false, false><<<g, 256>>>(
            q, k, nullptr, nullptr, sc, SEQ, CDIM, 0.044194173824159216f,
            (long)SEQ * CDIM, (long)SEQ * CDIM, (long)SEQ * SEQ);
    }

    // 4) softmax rows
    softmax_rows<<<BATCH * SEQ, 256>>>(sc);

    // 5) attn @ V, batched
    {
        dim3 g(CDIM / 64, SEQ / 128, BATCH);
        gemm_tf32<false, false, false><<<g, 256>>>(
            sc, v, nullptr, nullptr, at, CDIM, SEQ, 1.f,
            (long)SEQ * SEQ, (long)SEQ * CDIM, (long)SEQ * CDIM);
    }

    // 6) proj + bias + residual -> out
    {
        dim3 g(CDIM / 64, NTOK / 128, 1);
        gemm_tf32<false, true, true><<<g, 256>>>(at, Wp, bp, x, out, CDIM, CDIM, 1.f, 0, 0, 0);
    }
}

// round 6
// speedup vs baseline: 1.8068x; 1.8068x over previous
#include <cuda_runtime.h>
#include <cuda_bf16.h>
#include <stdint.h>
#include <math.h>

typedef __nv_bfloat16 bf16;

#define SEQ    4096
#define CDIM   512
#define BATCH  4
#define NTOK   (BATCH * SEQ)
#define GROUPS 32
#define EPSGN  1e-5f

// scratch (__device__ globals; allocation-free rule)
__device__ __align__(128) bf16 g_xn[(long)NTOK * CDIM];
__device__ __align__(128) bf16 g_q [(long)NTOK * CDIM];
__device__ __align__(128) bf16 g_k [(long)NTOK * CDIM];
__device__ __align__(128) bf16 g_v [(long)NTOK * CDIM];
__device__ __align__(128) bf16 g_vt[(long)NTOK * CDIM];
__device__ __align__(128) bf16 g_at[(long)NTOK * CDIM];
__device__ __align__(128) bf16 g_sc[(long)BATCH * SEQ * SEQ];
__device__ __align__(128) bf16 g_wt[4L * CDIM * CDIM];
__device__ float g_mean[BATCH * GROUPS];
__device__ float g_rstd[BATCH * GROUPS];

// ---------------- helpers (sm_80-portable PTX only) ----------------
__device__ __forceinline__ uint32_t s2u(const void* p) {
    uint32_t a;
    asm("{ .reg .u64 t; cvta.to.shared.u64 t, %1; cvt.u32.u64 %0, t; }" : "=r"(a) : "l"(p));
    return a;
}
__device__ __forceinline__ void cp16(uint32_t d, const void* s) {
    asm volatile("cp.async.cg.shared.global [%0], [%1], 16;"
                 :: "r"(d), "l"((unsigned long long)__cvta_generic_to_global(s)) : "memory");
}
#define CP_COMMIT() asm volatile("cp.async.commit_group;" ::: "memory")
#define CP_WAIT1()  asm volatile("cp.async.wait_group 1;" ::: "memory")

__device__ __forceinline__ void ldm4(uint32_t* r, uint32_t addr) {
    asm volatile("ldmatrix.sync.aligned.m8n8.x4.shared.b16 {%0,%1,%2,%3}, [%4];"
                 : "=r"(r[0]), "=r"(r[1]), "=r"(r[2]), "=r"(r[3]) : "r"(addr));
}
__device__ __forceinline__ void mma16(float* c, const uint32_t* a, uint32_t b0, uint32_t b1) {
    asm volatile(
        "mma.sync.aligned.m16n8k16.row.col.f32.bf16.bf16.f32 "
        "{%0,%1,%2,%3},{%4,%5,%6,%7},{%8,%9},{%0,%1,%2,%3};"
        : "+f"(c[0]), "+f"(c[1]), "+f"(c[2]), "+f"(c[3])
        : "r"(a[0]), "r"(a[1]), "r"(a[2]), "r"(a[3]), "r"(b0), "r"(b1));
}

// ---------------------------------------------------------------------------
// bf16 GEMM: C[M,N] = scale * A[M,K] @ B[N,K]^T (+bias) (+res, fp32 out)
// A [M,K], B [N,K] row-major bf16. Block 128x128x32, 8 warps (2x4) 64x32 each,
// 3-stage cp.async pipeline, ldmatrix.x4 fragments, smem row stride 40 bf16.
// ---------------------------------------------------------------------------
#define BM_ 128
#define BN_ 128
#define BK_ 32
#define AST 40                       // smem row stride in bf16 (80 B)
#define STG (2 * BM_ * AST)          // bf16 per stage (A+B) = 10240
#define DYN_SMEM (3 * STG * 2)       // bytes = 61440

template<bool BIAS, bool RES, bool F32OUT>
__global__ __launch_bounds__(256)
void gemm_bf16(const bf16* __restrict__ A, const bf16* __restrict__ Bm,
               const float* __restrict__ bias, const float* __restrict__ res,
               void* __restrict__ Cout, int N, int K, float scale,
               long sA, long sB, long sC)
{
    extern __shared__ bf16 sm[];
    const int tid = threadIdx.x, wid = tid >> 5, lane = tid & 31;
    const int bm = blockIdx.y * BM_, bn = blockIdx.x * BN_;
    A  += (long)blockIdx.z * sA;
    Bm += (long)blockIdx.z * sB;
    const long cOff = (long)blockIdx.z * sC;

    const uint32_t smb = s2u(sm);
    const int wm = (wid >> 2) * 64, wn = (wid & 3) * 32;
    const int lrow = ((lane >> 3) & 1) * 8 + (lane & 7);   // 0..15
    const int lkh  = (lane >> 4) * 8;                      // 0 or 8

    // cp.async indices: row = tid&127, chunks {c0, c0+2}
    const int grow = tid & 127, gc0 = tid >> 7;

    float acc[4][4][4];
#pragma unroll
    for (int mi = 0; mi < 4; mi++)
#pragma unroll
        for (int ni = 0; ni < 4; ni++)
#pragma unroll
            for (int j = 0; j < 4; j++) acc[mi][ni][j] = 0.f;

    const int KB = K / BK_;

    auto load_stage = [&](int s, int kb) {
        const long kc = (long)kb * BK_;
        const uint32_t as_ = smb + s * STG * 2;
        const uint32_t bs_ = as_ + BM_ * AST * 2;
#pragma unroll
        for (int i = 0; i < 2; i++) {
            const int ch = gc0 + 2 * i;
            cp16(as_ + (grow * AST + ch * 8) * 2, A + (long)(bm + grow) * K + kc + ch * 8);
            cp16(bs_ + (grow * AST + ch * 8) * 2, Bm + (long)(bn + grow) * K + kc + ch * 8);
        }
    };

    load_stage(0, 0); CP_COMMIT();
    load_stage(1, 1); CP_COMMIT();
    CP_WAIT1();
    __syncthreads();

    for (int kb = 0; kb < KB; kb++) {
        const int s = kb % 3;
        const uint32_t as_ = smb + s * STG * 2;
        const uint32_t bs_ = as_ + BM_ * AST * 2;

#pragma unroll
        for (int ks = 0; ks < BK_; ks += 16) {
            uint32_t af[4][4], bfr[2][4];
#pragma unroll
            for (int mi = 0; mi < 4; mi++)
                ldm4(af[mi], as_ + ((wm + mi * 16 + lrow) * AST + ks + lkh) * 2);
#pragma unroll
            for (int np = 0; np < 2; np++)
                ldm4(bfr[np], bs_ + ((wn + np * 16 + lrow) * AST + ks + lkh) * 2);
#pragma unroll
            for (int mi = 0; mi < 4; mi++)
#pragma unroll
                for (int ni = 0; ni < 4; ni++) {
                    const int np = ni >> 1, sel = ni & 1;
                    mma16(acc[mi][ni], af[mi], bfr[np][sel], bfr[np][sel + 2]);
                }
        }

        if (kb + 2 < KB) load_stage((kb + 2) % 3, kb + 2);
        CP_COMMIT();
        CP_WAIT1();
        __syncthreads();
    }

    // epilogue (direct reg -> gmem)
    const int g = lane >> 2, tq = lane & 3;
#pragma unroll
    for (int mi = 0; mi < 4; mi++) {
        const int r0 = bm + wm + mi * 16 + g;
#pragma unroll
        for (int ni = 0; ni < 4; ni++) {
            const int c = bn + wn + ni * 8 + tq * 2;
            float v00 = acc[mi][ni][0] * scale, v01 = acc[mi][ni][1] * scale;
            float v10 = acc[mi][ni][2] * scale, v11 = acc[mi][ni][3] * scale;
            if (BIAS) {
                const float b0 = bias[c], b1 = bias[c + 1];
                v00 += b0; v01 += b1; v10 += b0; v11 += b1;
            }
            if (F32OUT) {
                float* out = (float*)Cout + cOff;
                if (RES) {
                    v00 += res[cOff + (long)r0 * N + c];
                    v01 += res[cOff + (long)r0 * N + c + 1];
                    v10 += res[cOff + (long)(r0 + 8) * N + c];
                    v11 += res[cOff + (long)(r0 + 8) * N + c + 1];
                }
                *(float2*)(out + (long)r0 * N + c)       = make_float2(v00, v01);
                *(float2*)(out + (long)(r0 + 8) * N + c) = make_float2(v10, v11);
            } else {
                bf16* out = (bf16*)Cout + cOff;
                __nv_bfloat162 h0 = __float22bfloat162_rn(make_float2(v00, v01));
                __nv_bfloat162 h1 = __float22bfloat162_rn(make_float2(v10, v11));
                *(uint32_t*)(out + (long)r0 * N + c)       = *(uint32_t*)&h0;
                *(uint32_t*)(out + (long)(r0 + 8) * N + c) = *(uint32_t*)&h1;
            }
        }
    }
}

// ---------------- GroupNorm ----------------
__global__ __launch_bounds__(256)
void gn_stats(const float* __restrict__ x, float* __restrict__ mv, float* __restrict__ rv)
{
    __shared__ float rs[8], rs2[8];
    const int bg = blockIdx.x;
    const float* base = x + (long)(bg >> 5) * (SEQ * (long)CDIM) + (bg & 31) * 16;
    float s = 0.f, s2 = 0.f;
    for (int j = threadIdx.x; j < 16384; j += 256) {
        const float4 v = *(const float4*)(base + (long)(j >> 2) * CDIM + ((j & 3) << 2));
        s  += v.x + v.y + v.z + v.w;
        s2 += v.x * v.x + v.y * v.y + v.z * v.z + v.w * v.w;
    }
#pragma unroll
    for (int o = 16; o; o >>= 1) {
        s  += __shfl_xor_sync(0xffffffffu, s, o);
        s2 += __shfl_xor_sync(0xffffffffu, s2, o);
    }
    if ((threadIdx.x & 31) == 0) { rs[threadIdx.x >> 5] = s; rs2[threadIdx.x >> 5] = s2; }
    __syncthreads();
    if (threadIdx.x == 0) {
        float ts = 0.f, ts2 = 0.f;
#pragma unroll
        for (int i = 0; i < 8; i++) { ts += rs[i]; ts2 += rs2[i]; }
        const float mean = ts / 65536.f;
        const float var = ts2 / 65536.f - mean * mean;
        mv[bg] = mean;
        rv[bg] = rsqrtf(var + EPSGN);
    }
}

__global__ __launch_bounds__(256)
void gn_apply(const float* __restrict__ x, const float* __restrict__ gamma,
              const float* __restrict__ beta, const float* __restrict__ mv,
              const float* __restrict__ rv, bf16* __restrict__ xn)
{
    const long i8 = (long)blockIdx.x * 256 + threadIdx.x;
    const int c8 = (int)(i8 & 63);
    const int b = (int)(i8 >> 18);
    const int bg = b * 32 + (c8 >> 1);
    const float m = mv[bg], r = rv[bg];
    const float4 v0 = ((const float4*)x)[i8 * 2], v1 = ((const float4*)x)[i8 * 2 + 1];
    const float4 ga0 = ((const float4*)gamma)[c8 * 2], ga1 = ((const float4*)gamma)[c8 * 2 + 1];
    const float4 be0 = ((const float4*)beta)[c8 * 2],  be1 = ((const float4*)beta)[c8 * 2 + 1];
    bf16 o[8];
    o[0] = __float2bfloat16((v0.x - m) * r * ga0.x + be0.x);
    o[1] = __float2bfloat16((v0.y - m) * r * ga0.y + be0.y);
    o[2] = __float2bfloat16((v0.z - m) * r * ga0.z + be0.z);
    o[3] = __float2bfloat16((v0.w - m) * r * ga0.w + be0.w);
    o[4] = __float2bfloat16((v1.x - m) * r * ga1.x + be1.x);
    o[5] = __float2bfloat16((v1.y - m) * r * ga1.y + be1.y);
    o[6] = __float2bfloat16((v1.z - m) * r * ga1.z + be1.z);
    o[7] = __float2bfloat16((v1.w - m) * r * ga1.w + be1.w);
    ((uint4*)xn)[i8] = *(uint4*)o;
}

// ---------------- transposes ----------------
__global__ void wtrans(const float* __restrict__ W, bf16* __restrict__ Wt)
{
    __shared__ float tile[32][33];
    const int bx = blockIdx.x * 32, by = blockIdx.y * 32;
    const int tx = threadIdx.x, ty = threadIdx.y;
#pragma unroll
    for (int j = 0; j < 32; j += 8)
        tile[ty + j][tx] = W[(long)(by + ty + j) * CDIM + bx + tx];
    __syncthreads();
#pragma unroll
    for (int j = 0; j < 32; j += 8)
        Wt[(long)(bx + ty + j) * CDIM + by + tx] = __float2bfloat16(tile[tx][ty + j]);
}

__global__ void vtrans(const bf16* __restrict__ v, bf16* __restrict__ vt)
{
    __shared__ bf16 tile[32][33];
    const bf16* src = v + (long)blockIdx.z * SEQ * CDIM;
    bf16* dst = vt + (long)blockIdx.z * SEQ * CDIM;
    const int r0 = blockIdx.y * 32, c0 = blockIdx.x * 32;
    const int tx = threadIdx.x, ty = threadIdx.y;
#pragma unroll
    for (int j = 0; j < 32; j += 8)
        tile[ty + j][tx] = src[(long)(r0 + ty + j) * CDIM + c0 + tx];
    __syncthreads();
#pragma unroll
    for (int j = 0; j < 32; j += 8)
        dst[(long)(c0 + ty + j) * SEQ + r0 + tx] = tile[tx][ty + j];
}

// ---------------- softmax on bf16 rows of 4096 ----------------
__global__ __launch_bounds__(256)
void softmax_bf16(bf16* __restrict__ s)
{
    __shared__ float red[8];
    bf16* p = s + (long)blockIdx.x * SEQ;
    const int t = threadIdx.x;
    uint4 u[2];
    u[0] = ((uint4*)p)[t];
    u[1] = ((uint4*)p)[t + 256];
    float v[16];
#pragma unroll
    for (int j = 0; j < 2; j++) {
        const uint32_t* w = (const uint32_t*)&u[j];
#pragma unroll
        for (int q = 0; q < 4; q++) {
            float2 f = __bfloat1622float2(*(const __nv_bfloat162*)&w[q]);
            v[j * 8 + q * 2] = f.x; v[j * 8 + q * 2 + 1] = f.y;
        }
    }
    float m = -1e30f;
#pragma unroll
    for (int i = 0; i < 16; i++) m = fmaxf(m, v[i]);
#pragma unroll
    for (int o = 16; o; o >>= 1) m = fmaxf(m, __shfl_xor_sync(0xffffffffu, m, o));
    if ((t & 31) == 0) red[t >> 5] = m;
    __syncthreads();
    m = red[0];
#pragma unroll
    for (int i = 1; i < 8; i++) m = fmaxf(m, red[i]);
    __syncthreads();
    float sum = 0.f;
#pragma unroll
    for (int i = 0; i < 16; i++) { v[i] = __expf(v[i] - m); sum += v[i]; }
#pragma unroll
    for (int o = 16; o; o >>= 1) sum += __shfl_xor_sync(0xffffffffu, sum, o);
    if ((t & 31) == 0) red[t >> 5] = sum;
    __syncthreads();
    float tot = 0.f;
#pragma unroll
    for (int i = 0; i < 8; i++) tot += red[i];
    const float inv = 1.f / tot;
#pragma unroll
    for (int j = 0; j < 2; j++) {
        uint32_t* w = (uint32_t*)&u[j];
#pragma unroll
        for (int q = 0; q < 4; q++) {
            __nv_bfloat162 h = __float22bfloat162_rn(
                make_float2(v[j * 8 + q * 2] * inv, v[j * 8 + q * 2 + 1] * inv));
            w[q] = *(uint32_t*)&h;
        }
    }
    ((uint4*)p)[t] = u[0];
    ((uint4*)p)[t + 256] = u[1];
}

// ---------------- launcher ----------------
extern "C" void kernel_launch(void* const* d_in, const int* in_sizes, int n_in,
                              void* d_out, int out_size)
{
    const float* x     = (const float*)d_in[0];
    const float* gamma = (const float*)d_in[1];
    const float* beta  = (const float*)d_in[2];
    const float* Wq    = (const float*)d_in[3];
    const float* bq    = (const float*)d_in[4];
    const float* Wk    = (const float*)d_in[5];
    const float* bk    = (const float*)d_in[6];
    const float* Wv    = (const float*)d_in[7];
    const float* bv    = (const float*)d_in[8];
    const float* Wp    = (const float*)d_in[9];
    const float* bp    = (const float*)d_in[10];
    float* out = (float*)d_out;

    void *pxn, *pq, *pk, *pv, *pvt, *pat, *psc, *pwt, *pm, *pr;
    cudaGetSymbolAddress(&pxn, g_xn);
    cudaGetSymbolAddress(&pq,  g_q);
    cudaGetSymbolAddress(&pk,  g_k);
    cudaGetSymbolAddress(&pv,  g_v);
    cudaGetSymbolAddress(&pvt, g_vt);
    cudaGetSymbolAddress(&pat, g_at);
    cudaGetSymbolAddress(&psc, g_sc);
    cudaGetSymbolAddress(&pwt, g_wt);
    cudaGetSymbolAddress(&pm,  g_mean);
    cudaGetSymbolAddress(&pr,  g_rstd);
    bf16* xn = (bf16*)pxn;
    bf16* q  = (bf16*)pq;
    bf16* k  = (bf16*)pk;
    bf16* v  = (bf16*)pv;
    bf16* vt = (bf16*)pvt;
    bf16* at = (bf16*)pat;
    bf16* sc = (bf16*)psc;
    bf16* wt = (bf16*)pwt;
    float* mv = (float*)pm;
    float* rv = (float*)pr;

    cudaFuncSetAttribute(gemm_bf16<true,  false, false>, cudaFuncAttributeMaxDynamicSharedMemorySize, DYN_SMEM);
    cudaFuncSetAttribute(gemm_bf16<false, false, false>, cudaFuncAttributeMaxDynamicSharedMemorySize, DYN_SMEM);
    cudaFuncSetAttribute(gemm_bf16<true,  true,  true >, cudaFuncAttributeMaxDynamicSharedMemorySize, DYN_SMEM);

    const long WSZ = (long)CDIM * CDIM;

    // weight transpose + bf16 convert
    {
        dim3 tb(32, 8), tg(16, 16);
        wtrans<<<tg, tb>>>(Wq, wt + 0 * WSZ);
        wtrans<<<tg, tb>>>(Wk, wt + 1 * WSZ);
        wtrans<<<tg, tb>>>(Wv, wt + 2 * WSZ);
        wtrans<<<tg, tb>>>(Wp, wt + 3 * WSZ);
    }

    // GroupNorm
    gn_stats<<<BATCH * GROUPS, 256>>>(x, mv, rv);
    gn_apply<<<(NTOK * CDIM) / (256 * 8), 256>>>(x, gamma, beta, mv, rv, xn);

    // QKV projections: [16384,512] @ Wt[512,512]^T
    {
        dim3 g(CDIM / BN_, NTOK / BM_, 1);
        gemm_bf16<true, false, false><<<g, 256, DYN_SMEM>>>(xn, wt + 0 * WSZ, bq, nullptr, q, CDIM, CDIM, 1.f, 0, 0, 0);
        gemm_bf16<true, false, false><<<g, 256, DYN_SMEM>>>(xn, wt + 1 * WSZ, bk, nullptr, k, CDIM, CDIM, 1.f, 0, 0, 0);
        gemm_bf16<true, false, false><<<g, 256, DYN_SMEM>>>(xn, wt + 2 * WSZ, bv, nullptr, v, CDIM, CDIM, 1.f, 0, 0, 0);
    }

    // V transpose (per batch): [4096,512] -> [512,4096]
    vtrans<<<dim3(CDIM / 32, SEQ / 32, BATCH), dim3(32, 8)>>>(v, vt);

    // scores = Q K^T / sqrt(C)
    {
        dim3 g(SEQ / BN_, SEQ / BM_, BATCH);
        gemm_bf16<false, false, false><<<g, 256, DYN_SMEM>>>(
            q, k, nullptr, nullptr, sc, SEQ, CDIM, 0.044194173824159216f,
            (long)SEQ * CDIM, (long)SEQ * CDIM, (long)SEQ * SEQ);
    }

    // softmax
    softmax_bf16<<<BATCH * SEQ, 256>>>(sc);

    // attn @ V : P[4096,4096] @ vt[512,4096]^T
    {
        dim3 g(CDIM / BN_, SEQ / BM_, BATCH);
        gemm_bf16<false, false, false><<<g, 256, DYN_SMEM>>>(
            sc, vt, nullptr, nullptr, at, CDIM, SEQ, 1.f,
            (long)SEQ * SEQ, (long)SEQ * CDIM, (long)SEQ * CDIM);
    }

    // proj + bias + residual -> out (fp32)
    {
        dim3 g(CDIM / BN_, NTOK / BM_, 1);
        gemm_bf16<true, true, true><<<g, 256, DYN_SMEM>>>(
            at, wt + 3 * WSZ, bp, x, out, CDIM, CDIM, 1.f, 0, 0, 0);
    }
}